// round 16
// baseline (speedup 1.0000x reference)
#include <cuda_runtime.h>

// Problem constants: x[16,128,8192] f32, weights1[128,128,2048] f32,
// output [16,128,4097] f32.
#define B_     16
#define CIN_   128
#define COUT_  128
#define N_     8192
#define MODES_ 2048
#define LOUT_  4097

#define NROWS    (B_ * CIN_)                 // 2048 reader rows
#define NBLK     1024                        // single-wave persistent grid
#define OUT4     ((B_ * COUT_ * LOUT_) / 4)  // 2097664 float4
#define W4_MAIN  2048                        // float4 per writer slice (32KB)
#define W4_REM   (OUT4 - NBLK * W4_MAIN)     // 512 remainder float4 (no head elems)

// Head accumulators, zero-init at load; each replay's finishers reset to 0.
__device__ float g_acc[B_ * COUT_];
// Per-batch monotonic tickets (64 arrivals/replay, power of 2 -> wrap-safe).
__device__ unsigned g_ctr_b[B_];

__device__ __forceinline__ unsigned ticket_acq_rel(unsigned* p) {
    unsigned t;
    asm volatile("atom.add.acq_rel.gpu.global.u32 %0, [%1], 1;"
                 : "=r"(t) : "l"(p) : "memory");
    return t;
}
__device__ __forceinline__ float ld_cg(const float* p) {
    float v;
    asm volatile("ld.global.cg.f32 %0, [%1];" : "=f"(v) : "l"(p) : "memory");
    return v;
}

// ---------------------------------------------------------------------------
// Single-wave kernel: 1024 blocks, each block g does (in order):
//   1. WRITER: zero-stores of out slice [g*8192, (g+1)*8192) elements with
//      DEFAULT cache policy -> out's dirty lines stay L2-resident across
//      graph replays (re-dirtied in place; writeback deferred), skipping the
//      <=2 head elements (index r*4097) inside the slice; block 0 also
//      zeroes the 2KB remainder (contains no head elements).
//   2. DUAL READER: rows 2g and 2g+1 (same b), EVICT-FIRST (__ldcs) loads so
//      the 64MB x stream doesn't evict out from L2.
//   3. HEAD: tid<128 does ONE atomicAdd of S0*w[i0,o,0] + S1*w[i1,o,0];
//      per-b acq_rel ticket; 64th arrival writes out[b,o,0] and resets g_acc.
// ---------------------------------------------------------------------------
__global__ void __launch_bounds__(256) fused_kernel(const float* __restrict__ x,
                                                    const float* __restrict__ w,
                                                    float* __restrict__ out) {
    const int g   = blockIdx.x;            // 0..1023
    const int tid = threadIdx.x;

    // ---- head-weight prefetch for both rows (hide latency under stores) ----
    const int row0 = 2 * g;
    const int b    = row0 >> 7;
    const int i0   = row0 & (CIN_ - 1);
    float wv0 = 0.0f, wv1 = 0.0f;
    if (tid < COUT_) {
        wv0 = __ldg(&w[(size_t)(i0 * COUT_ + tid) * MODES_]);
        wv1 = __ldg(&w[(size_t)((i0 + 1) * COUT_ + tid) * MODES_]);
    }

    // ------------------------------ WRITER ---------------------------------
    {
        const long long e0 = (long long)g * (W4_MAIN * 4);
        const long long e1 = e0 + W4_MAIN * 4;
        const int r_lo = (int)((e0 + LOUT_ - 1) / LOUT_);
        int sp0 = -1, sp1 = -1;
        if (r_lo < NROWS && (long long)r_lo * LOUT_ < e1)
            sp0 = (int)((long long)r_lo * LOUT_ - e0);
        if (r_lo + 1 < NROWS && (long long)(r_lo + 1) * LOUT_ < e1)
            sp1 = (int)((long long)(r_lo + 1) * LOUT_ - e0);
        const int sp0f4 = sp0 >> 2, sp1f4 = sp1 >> 2;

        float4 z = make_float4(0.0f, 0.0f, 0.0f, 0.0f);
        float4* o4 = reinterpret_cast<float4*>(out) + (size_t)g * W4_MAIN;
        #pragma unroll
        for (int j = 0; j < W4_MAIN / 256; j++) {
            const int idx = tid + j * 256;
            if (idx != sp0f4 && idx != sp1f4) {
                o4[idx] = z;                       // default policy: L2-resident
            } else {
                const int sc = (idx == sp0f4) ? (sp0 & 3) : (sp1 & 3);
                float* os = reinterpret_cast<float*>(o4 + idx);
                #pragma unroll
                for (int c = 0; c < 4; c++)
                    if (c != sc) os[c] = 0.0f;
            }
        }
        if (g == 0) {
            float4* orem = reinterpret_cast<float4*>(out) + (size_t)NBLK * W4_MAIN;
            #pragma unroll
            for (int j = 0; j < W4_REM / 256; j++)
                orem[tid + j * 256] = z;
        }
    }

    // --------------------------- DUAL READER --------------------------------
    const float4* __restrict__ xr0 =
        reinterpret_cast<const float4*>(x) + (size_t)row0 * (N_ / 4);
    const float4* __restrict__ xr1 = xr0 + (N_ / 4);
    float sum0 = 0.0f, sum1 = 0.0f;
    #pragma unroll
    for (int j = 0; j < (N_ / 4) / 256; j++) {
        float4 v0 = __ldcs(&xr0[tid + j * 256]);   // evict-first: protect out in L2
        float4 v1 = __ldcs(&xr1[tid + j * 256]);
        sum0 += (v0.x + v0.y) + (v0.z + v0.w);
        sum1 += (v1.x + v1.y) + (v1.z + v1.w);
    }
    #pragma unroll
    for (int off = 16; off > 0; off >>= 1) {
        sum0 += __shfl_xor_sync(0xffffffffu, sum0, off);
        sum1 += __shfl_xor_sync(0xffffffffu, sum1, off);
    }

    __shared__ float2 wsum[8];
    __shared__ float2 Sb;
    const int lane = tid & 31;
    const int wid  = tid >> 5;
    if (lane == 0) wsum[wid] = make_float2(sum0, sum1);
    __syncthreads();
    if (wid == 0) {
        float2 sv = (lane < 8) ? wsum[lane] : make_float2(0.0f, 0.0f);
        float s0 = sv.x, s1 = sv.y;
        #pragma unroll
        for (int off = 4; off > 0; off >>= 1) {
            s0 += __shfl_xor_sync(0xffffffffu, s0, off);
            s1 += __shfl_xor_sync(0xffffffffu, s1, off);
        }
        if (lane == 0) Sb = make_float2(s0, s1);
    }
    __syncthreads();
    const float S0 = Sb.x, S1 = Sb.y;

    // ------------------------------- HEAD -----------------------------------
    if (tid < COUT_)
        atomicAdd(&g_acc[b * COUT_ + tid], S0 * wv0 + S1 * wv1);
    __syncthreads();                       // atomics issued before ticket

    __shared__ unsigned ts;
    if (tid == 0) ts = ticket_acq_rel(&g_ctr_b[b]);
    __syncthreads();
    const unsigned rank = ts & 63u;        // 64 pair-arrivals per b per replay

    if (rank == 63u) {
        // finisher: acq_rel RMW saw all prior releases for this b.
        if (tid < COUT_) {
            float a = ld_cg(&g_acc[b * COUT_ + tid]);
            out[(size_t)(b * COUT_ + tid) * LOUT_] = a * (1.0f / 4097.0f);
            g_acc[b * COUT_ + tid] = 0.0f; // reset for next replay
        }
    }
}

// ---------------------------------------------------------------------------
extern "C" void kernel_launch(void* const* d_in, const int* in_sizes, int n_in,
                              void* d_out, int out_size) {
    const float* x = (const float*)d_in[0];
    const float* w = (const float*)d_in[1];
    float* out = (float*)d_out;

    fused_kernel<<<NBLK, 256>>>(x, w, out);
}